// round 11
// baseline (speedup 1.0000x reference)
#include <cuda_runtime.h>
#include <cuda_fp16.h>
#include <math.h>
#include <stdint.h>

#define HW    2560
#define TT    16
#define HEADS 8
#define DH    64
#define QD    512
#define MTOT  (HW * TT)      // 40960
#define SCALE 0.125f

// ---------------- scratch (device globals: allocation-free) ----------------
__device__ float g_q[(size_t)MTOT * QD];
__device__ float g_k[(size_t)MTOT * QD];
__device__ float g_v[(size_t)MTOT * QD];
__device__ __half g_xh[(size_t)MTOT * QD];
__device__ __half g_xl[(size_t)MTOT * QD];
__device__ __half g_ath[(size_t)MTOT * QD];
__device__ __half g_atl[(size_t)MTOT * QD];
__device__ __half g_wt[(size_t)4 * QD * QD];    // Wt[w][n][k] fp16

// ---------------- helpers --------------------------------------------------
__device__ __forceinline__ uint32_t smem_u32(const void* p) {
    uint32_t a;
    asm("{ .reg .u64 t; cvta.to.shared.u64 t, %1; cvt.u32.u64 %0, t; }" : "=r"(a) : "l"(p));
    return a;
}
__device__ __forceinline__ void mma16816h(float* d, const uint32_t* a, const uint32_t* b) {
    asm volatile(
        "mma.sync.aligned.m16n8k16.row.col.f32.f16.f16.f32 "
        "{%0,%1,%2,%3}, {%4,%5,%6,%7}, {%8,%9}, {%0,%1,%2,%3};"
        : "+f"(d[0]), "+f"(d[1]), "+f"(d[2]), "+f"(d[3])
        : "r"(a[0]), "r"(a[1]), "r"(a[2]), "r"(a[3]), "r"(b[0]), "r"(b[1]));
}
__device__ __forceinline__ void cp16(uint32_t dst, const void* src) {
    asm volatile("cp.async.ca.shared.global [%0], [%1], 16;" :: "r"(dst), "l"(src));
}
#define CP_COMMIT() asm volatile("cp.async.commit_group;" ::: "memory")
#define CP_WAIT1()  asm volatile("cp.async.wait_group 1;" ::: "memory")
#define CP_WAIT0()  asm volatile("cp.async.wait_group 0;" ::: "memory")

// ---------------- split passes ---------------------------------------------
__global__ __launch_bounds__(256)
void split_x(const float* __restrict__ X, __half* __restrict__ xh,
             __half* __restrict__ xl) {
    size_t i = (size_t)blockIdx.x * 256 + threadIdx.x;
    float2 a = ((const float2*)X)[i];
    __half hx = __float2half(a.x);
    __half hy = __float2half(a.y);
    __half lx = __float2half(a.x - __half2float(hx));
    __half ly = __float2half(a.y - __half2float(hy));
    ((__half2*)xh)[i] = __halves2half2(hx, hy);
    ((__half2*)xl)[i] = __halves2half2(lx, ly);
}

// transpose the 4 weight matrices to fp16: Wt[w][n][k] = fp16(W[k][n])
__global__ __launch_bounds__(256)
void split_w(const float* __restrict__ W0, const float* __restrict__ W1,
             const float* __restrict__ W2, const float* __restrict__ W3,
             __half* __restrict__ wt) {
    __shared__ float t[32][33];
    const int w = blockIdx.z;
    const float* W = (w == 0) ? W0 : (w == 1) ? W1 : (w == 2) ? W2 : W3;
    const int tx = threadIdx.x, ty = threadIdx.y;
#pragma unroll
    for (int i = 0; i < 4; i++)
        t[ty + 8 * i][tx] = W[(size_t)(blockIdx.y * 32 + ty + 8 * i) * QD + blockIdx.x * 32 + tx];
    __syncthreads();
#pragma unroll
    for (int i = 0; i < 4; i++) {
        int n = blockIdx.x * 32 + ty + 8 * i;
        int k = blockIdx.y * 32 + tx;
        wt[((size_t)w * QD + n) * QD + k] = __float2half(t[tx][ty + 8 * i]);
    }
}

// ======== fp16 2-term GEMM: C = (Ah+Al) @ B, fp32 accum ====================
// CTA 128x128, BK=32, 256 thr, 4(m)x2(n) warp grid, 32x64 warp tiles.
// 3 smem tiles per stage: Ah, Al, B. Double buffered via cp.async.
#define BKC   32
#define SPADW 20                    // row stride in words (40 fp16)
#define TILEB (128 * 80)            // 10240 B per tile
#define BUFB  (3 * TILEB)           // 30720 B per stage
#define GDYN  (2 * BUFB)            // 61440 B

__device__ __forceinline__ void gemm_prefetch(
    uint32_t sbase, int b, int kc, int tid, int m0, int n0,
    const __half* Ah, const __half* Al, const __half* Bt) {
#pragma unroll
    for (int i = 0; i < 6; i++) {
        int e = tid + i * 256;
        int tile = e >> 9;
        int r    = (e >> 2) & 127;
        int c16  = e & 3;
        uint32_t dst = sbase + b * BUFB + tile * TILEB + r * 80 + c16 * 16;
        const __half* src;
        if (tile == 0)      src = Ah + (size_t)(m0 + r) * QD + kc * BKC + c16 * 8;
        else if (tile == 1) src = Al + (size_t)(m0 + r) * QD + kc * BKC + c16 * 8;
        else                src = Bt + (size_t)(n0 + r) * QD + kc * BKC + c16 * 8;
        cp16(dst, src);
    }
    CP_COMMIT();
}

// z selects weight w and output C; bias != nullptr -> add bias.
__global__ __launch_bounds__(256, 2)
void gemm_h(const __half* __restrict__ Ah, const __half* __restrict__ Al,
            const __half* __restrict__ Wt, const float* __restrict__ bias,
            float* __restrict__ C0, float* __restrict__ C1, float* __restrict__ C2) {
    extern __shared__ char dsm[];
    const uint32_t sbase = smem_u32(dsm);

    const int tid = threadIdx.x;
    const int wid = tid >> 5, lid = tid & 31;
    const int wm = wid & 3, wn = wid >> 2;      // 4(m) x 2(n)
    const int g = lid >> 2, t = lid & 3;
    const int m0 = blockIdx.y * 128;
    const int n0 = blockIdx.x * 128;
    const int w  = blockIdx.z;
    float* C = (w == 0) ? C0 : (w == 1) ? C1 : C2;
    const __half* Bt = Wt + (size_t)w * QD * QD;

    float acc[2][8][4];
#pragma unroll
    for (int mi = 0; mi < 2; mi++)
#pragma unroll
        for (int ni = 0; ni < 8; ni++)
#pragma unroll
            for (int c = 0; c < 4; c++) acc[mi][ni][c] = 0.0f;

    gemm_prefetch(sbase, 0, 0, tid, m0, n0, Ah, Al, Bt);

    for (int kc = 0; kc < QD / BKC; kc++) {
        const int last = (kc == QD / BKC - 1);
        if (!last) gemm_prefetch(sbase, (kc + 1) & 1, kc + 1, tid, m0, n0, Ah, Al, Bt);
        if (!last) CP_WAIT1(); else CP_WAIT0();
        __syncthreads();

        const int b = kc & 1;
        const uint32_t* AshW = (const uint32_t*)(dsm + b * BUFB);
        const uint32_t* AslW = (const uint32_t*)(dsm + b * BUFB + TILEB);
        const uint32_t* BsW  = (const uint32_t*)(dsm + b * BUFB + 2 * TILEB);

#pragma unroll
        for (int ks = 0; ks < 2; ks++) {
            const int c0w = ks * 8 + t;
            uint32_t bh[8][2];
#pragma unroll
            for (int ni = 0; ni < 8; ni++) {
                int n = wn * 64 + ni * 8 + g;
                bh[ni][0] = BsW[n * SPADW + c0w];
                bh[ni][1] = BsW[n * SPADW + c0w + 4];
            }
#pragma unroll
            for (int mi = 0; mi < 2; mi++) {
                int r = wm * 32 + mi * 16 + g;
                uint32_t ah[4], al[4];
                ah[0] = AshW[r * SPADW + c0w];
                ah[1] = AshW[(r + 8) * SPADW + c0w];
                ah[2] = AshW[r * SPADW + c0w + 4];
                ah[3] = AshW[(r + 8) * SPADW + c0w + 4];
                al[0] = AslW[r * SPADW + c0w];
                al[1] = AslW[(r + 8) * SPADW + c0w];
                al[2] = AslW[r * SPADW + c0w + 4];
                al[3] = AslW[(r + 8) * SPADW + c0w + 4];
#pragma unroll
                for (int ni = 0; ni < 8; ni++) {
                    mma16816h(acc[mi][ni], ah, bh[ni]);
                    mma16816h(acc[mi][ni], al, bh[ni]);
                }
            }
        }
        __syncthreads();
    }

#pragma unroll
    for (int mi = 0; mi < 2; mi++) {
        int r = m0 + wm * 32 + mi * 16 + g;
#pragma unroll
        for (int ni = 0; ni < 8; ni++) {
            int col = n0 + wn * 64 + ni * 8 + t * 2;
            float b0 = 0.f, b1 = 0.f;
            if (bias) { b0 = bias[col]; b1 = bias[col + 1]; }
            float2 v0, v1;
            v0.x = acc[mi][ni][0] + b0; v0.y = acc[mi][ni][1] + b1;
            v1.x = acc[mi][ni][2] + b0; v1.y = acc[mi][ni][3] + b1;
            *(float2*)&C[(size_t)r * QD + col] = v0;
            *(float2*)&C[(size_t)(r + 8) * QD + col] = v1;
        }
    }
}

// ---------------- Attention core (R8-proven): one CTA per (hw, head) -------
struct Boxes { int hs[TT]; int ws[TT]; int sub_h; int sub_w; };

__global__ __launch_bounds__(256)
void attn_kernel(const float* __restrict__ Q, const float* __restrict__ K,
                 const float* __restrict__ V, const float* __restrict__ RK,
                 const float* __restrict__ RV,
                 __half* __restrict__ ATH, __half* __restrict__ ATL,
                 Boxes bx) {
    const int hw = blockIdx.x;
    const int h  = blockIdx.y;
    const int tid = threadIdx.x;

    __shared__ float qs[TT][DH + 1];
    __shared__ float kst[DH][TT + 1];
    __shared__ float vs[TT][DH];
    __shared__ float rkt[DH][34];
    __shared__ float rvs[33][DH];
    __shared__ float sims[TT][TT + 1];

    const size_t base = ((size_t)hw * TT) * QD + h * DH;
#pragma unroll
    for (int e = tid; e < TT * DH; e += 256) {
        int t = e >> 6, d = e & 63;
        size_t gi = base + (size_t)t * QD + d;
        qs[t][d]  = Q[gi];
        kst[d][t] = K[gi];
        vs[t][d]  = V[gi];
    }
#pragma unroll
    for (int e = tid; e < 33 * DH; e += 256) {
        int r = e >> 6, d = e & 63;
        rkt[d][r] = RK[e];
        rvs[r][d] = RV[e];
    }
    __syncthreads();

    const int y = hw / 40, x = hw % 40;
    unsigned fg = 0;
#pragma unroll
    for (int t = 0; t < TT; t++) {
        int inb = (y >= bx.hs[t]) & (y < bx.hs[t] + bx.sub_h) &
                  (x >= bx.ws[t]) & (x < bx.ws[t] + bx.sub_w);
        fg |= (unsigned)inb << t;
    }

    {
        const int i = tid >> 4, j = tid & 15;
        const int r = j - i + 16;
        float s = 0.0f, sr = 0.0f;
#pragma unroll
        for (int d = 0; d < DH; d++) {
            float qv = qs[i][d];
            s  = fmaf(qv, kst[d][j], s);
            sr = fmaf(qv, rkt[d][r], sr);
        }
        float m = (((fg >> i) & 1u) == ((fg >> j) & 1u)) ? 1.0f : 0.01f;
        sims[i][j] = (s + sr) * SCALE * m;
    }
    __syncthreads();

    if (tid < TT) {
        float mx = -1e30f;
#pragma unroll
        for (int j = 0; j < TT; j++) mx = fmaxf(mx, sims[tid][j]);
        float sum = 0.0f;
#pragma unroll
        for (int j = 0; j < TT; j++) {
            float e = expf(sims[tid][j] - mx);
            sims[tid][j] = e;
            sum += e;
        }
        float inv = 1.0f / sum;
#pragma unroll
        for (int j = 0; j < TT; j++) sims[tid][j] *= inv;
    }
    __syncthreads();

#pragma unroll
    for (int e = tid; e < TT * DH; e += 256) {
        int i = e >> 6, d = e & 63;
        float o = 0.0f;
#pragma unroll
        for (int j = 0; j < TT; j++) {
            o = fmaf(sims[i][j], vs[j][d] + rvs[j - i + 16][d], o);
        }
        __half oh = __float2half(o);
        __half ol = __float2half(o - __half2float(oh));
        ATH[base + (size_t)i * QD + d] = oh;
        ATL[base + (size_t)i * QD + d] = ol;
    }
}

// ---------------------------- launcher -------------------------------------
extern "C" void kernel_launch(void* const* d_in, const int* in_sizes, int n_in,
                              void* d_out, int out_size) {
    const float* x     = (const float*)d_in[0];
    const float* Wq    = (const float*)d_in[1];
    const float* Wk    = (const float*)d_in[2];
    const float* Wv    = (const float*)d_in[3];
    const float* Wo    = (const float*)d_in[4];
    const float* bo    = (const float*)d_in[5];
    const float* rel_k = (const float*)d_in[6];
    const float* rel_v = (const float*)d_in[7];
    float* out = (float*)d_out;

    float *q, *k, *v;
    __half *xh, *xl, *ath, *atl, *wt;
    cudaGetSymbolAddress((void**)&q,   g_q);
    cudaGetSymbolAddress((void**)&k,   g_k);
    cudaGetSymbolAddress((void**)&v,   g_v);
    cudaGetSymbolAddress((void**)&xh,  g_xh);
    cudaGetSymbolAddress((void**)&xl,  g_xl);
    cudaGetSymbolAddress((void**)&ath, g_ath);
    cudaGetSymbolAddress((void**)&atl, g_atl);
    cudaGetSymbolAddress((void**)&wt,  g_wt);

    // Box path (exact binary64 semantics): SUB_H=15, SUB_W=9
    Boxes bx;
    bx.sub_h = (int)((0.35 - 0.10) * 64.0);
    bx.sub_w = (int)((0.35 - 0.10) * 40.0);
    for (int t = 0; t < TT; t++) {
        double r  = (double)t / 15.0;
        double h0 = 0.10 + r * (0.60 - 0.10);
        double w0 = 0.10 + r * (0.60 - 0.10);
        bx.hs[t] = (int)(h0 * 64.0);
        bx.ws[t] = (int)(w0 * 40.0);
    }

    cudaFuncSetAttribute(gemm_h, cudaFuncAttributeMaxDynamicSharedMemorySize, GDYN);

    split_x<<<MTOT * QD / 512, 256>>>(x, xh, xl);
    split_w<<<dim3(16, 16, 4), dim3(32, 8)>>>(Wq, Wk, Wv, Wo, wt);

    // fused QKV: z selects weight & output
    gemm_h<<<dim3(4, 320, 3), 256, GDYN>>>(xh, xl, wt, nullptr, q, k, v);

    attn_kernel<<<dim3(HW, HEADS), 256>>>(q, k, v, rel_k, rel_v, ath, atl, bx);

    // output projection: weight index 3 (pre-offset), + bias
    gemm_h<<<dim3(4, 320, 1), 256, GDYN>>>(ath, atl,
                                           wt + (size_t)3 * QD * QD,
                                           bo, out, out, out);
}

// round 12
// speedup vs baseline: 1.5532x; 1.5532x over previous
#include <cuda_runtime.h>
#include <cuda_fp16.h>
#include <math.h>
#include <stdint.h>

#define HW    2560
#define TT    16
#define HEADS 8
#define DH    64
#define QD    512
#define MTOT  (HW * TT)      // 40960
#define SCALE 0.125f

// ---------------- scratch (device globals: allocation-free) ----------------
__device__ float g_q[(size_t)MTOT * QD];
__device__ float g_k[(size_t)MTOT * QD];
__device__ float g_v[(size_t)MTOT * QD];
__device__ __half g_xh[(size_t)MTOT * QD];
__device__ __half g_xl[(size_t)MTOT * QD];
__device__ __half g_ath[(size_t)MTOT * QD];
__device__ __half g_atl[(size_t)MTOT * QD];
__device__ __half g_wt[(size_t)4 * QD * QD];    // Wt[w][n][k] fp16

// ---------------- helpers --------------------------------------------------
__device__ __forceinline__ uint32_t smem_u32(const void* p) {
    uint32_t a;
    asm("{ .reg .u64 t; cvta.to.shared.u64 t, %1; cvt.u32.u64 %0, t; }" : "=r"(a) : "l"(p));
    return a;
}
__device__ __forceinline__ void mma16816h(float* d, const uint32_t* a, const uint32_t* b) {
    asm volatile(
        "mma.sync.aligned.m16n8k16.row.col.f32.f16.f16.f32 "
        "{%0,%1,%2,%3}, {%4,%5,%6,%7}, {%8,%9}, {%0,%1,%2,%3};"
        : "+f"(d[0]), "+f"(d[1]), "+f"(d[2]), "+f"(d[3])
        : "r"(a[0]), "r"(a[1]), "r"(a[2]), "r"(a[3]), "r"(b[0]), "r"(b[1]));
}
__device__ __forceinline__ void cp16(uint32_t dst, const void* src) {
    asm volatile("cp.async.ca.shared.global [%0], [%1], 16;" :: "r"(dst), "l"(src));
}
#define CP_COMMIT() asm volatile("cp.async.commit_group;" ::: "memory")
#define CP_WAIT1()  asm volatile("cp.async.wait_group 1;" ::: "memory")
#define CP_WAIT0()  asm volatile("cp.async.wait_group 0;" ::: "memory")

// ---------------- split passes ---------------------------------------------
__global__ __launch_bounds__(256)
void split_x(const float* __restrict__ X, __half* __restrict__ xh,
             __half* __restrict__ xl) {
    size_t i = (size_t)blockIdx.x * 256 + threadIdx.x;
    float2 a = ((const float2*)X)[i];
    __half hx = __float2half(a.x);
    __half hy = __float2half(a.y);
    __half lx = __float2half(a.x - __half2float(hx));
    __half ly = __float2half(a.y - __half2float(hy));
    ((__half2*)xh)[i] = __halves2half2(hx, hy);
    ((__half2*)xl)[i] = __halves2half2(lx, ly);
}

// transpose the 4 weight matrices to fp16: Wt[w][n][k] = fp16(W[k][n])
__global__ __launch_bounds__(256)
void split_w(const float* __restrict__ W0, const float* __restrict__ W1,
             const float* __restrict__ W2, const float* __restrict__ W3,
             __half* __restrict__ wt) {
    __shared__ float t[32][33];
    const int w = blockIdx.z;
    const float* W = (w == 0) ? W0 : (w == 1) ? W1 : (w == 2) ? W2 : W3;
    const int tx = threadIdx.x, ty = threadIdx.y;
#pragma unroll
    for (int i = 0; i < 4; i++)
        t[ty + 8 * i][tx] = W[(size_t)(blockIdx.y * 32 + ty + 8 * i) * QD + blockIdx.x * 32 + tx];
    __syncthreads();
#pragma unroll
    for (int i = 0; i < 4; i++) {
        int n = blockIdx.x * 32 + ty + 8 * i;
        int k = blockIdx.y * 32 + tx;
        wt[((size_t)w * QD + n) * QD + k] = __float2half(t[tx][ty + 8 * i]);
    }
}

// ======== fp16 2-term GEMM: C = (Ah+Al) @ B, fp32 accum ====================
// CTA 128x128, BK=32, 256 thr, 4(m)x2(n) warp grid, 32x64 warp tiles.
// 3 smem tiles per stage (Ah, Al, B), double buffered via cp.async.
#define BKC   32
#define SPADW 20                    // row stride in words (40 fp16)
#define TILEB (128 * 80)            // 10240 B per tile
#define BUFB  (3 * TILEB)           // 30720 B per stage
#define GDYN  (2 * BUFB)            // 61440 B

__device__ __forceinline__ void gemm_prefetch(
    uint32_t sbase, int b, int kc, int tid, int m0, int n0,
    const __half* Ah, const __half* Al, const __half* Bt) {
#pragma unroll
    for (int i = 0; i < 6; i++) {
        int e = tid + i * 256;
        int tile = e >> 9;
        int r    = (e >> 2) & 127;
        int c16  = e & 3;
        uint32_t dst = sbase + b * BUFB + tile * TILEB + r * 80 + c16 * 16;
        const __half* src;
        if (tile == 0)      src = Ah + (size_t)(m0 + r) * QD + kc * BKC + c16 * 8;
        else if (tile == 1) src = Al + (size_t)(m0 + r) * QD + kc * BKC + c16 * 8;
        else                src = Bt + (size_t)(n0 + r) * QD + kc * BKC + c16 * 8;
        cp16(dst, src);
    }
    CP_COMMIT();
}

// z selects weight w and output C; bias != nullptr -> add bias.
__global__ __launch_bounds__(256, 2)
void gemm_h(const __half* __restrict__ Ah, const __half* __restrict__ Al,
            const __half* __restrict__ Wt, const float* __restrict__ bias,
            float* __restrict__ C0, float* __restrict__ C1, float* __restrict__ C2) {
    extern __shared__ char dsm[];
    const uint32_t sbase = smem_u32(dsm);

    const int tid = threadIdx.x;
    const int wid = tid >> 5, lid = tid & 31;
    const int wm = wid & 3, wn = wid >> 2;      // 4(m) x 2(n)
    const int g = lid >> 2, t = lid & 3;
    const int m0 = blockIdx.y * 128;
    const int n0 = blockIdx.x * 128;
    const int w  = blockIdx.z;
    float* C = (w == 0) ? C0 : (w == 1) ? C1 : C2;
    const __half* Bt = Wt + (size_t)w * QD * QD;

    float acc[2][8][4];
#pragma unroll
    for (int mi = 0; mi < 2; mi++)
#pragma unroll
        for (int ni = 0; ni < 8; ni++)
#pragma unroll
            for (int c = 0; c < 4; c++) acc[mi][ni][c] = 0.0f;

    gemm_prefetch(sbase, 0, 0, tid, m0, n0, Ah, Al, Bt);

    for (int kc = 0; kc < QD / BKC; kc++) {
        const int last = (kc == QD / BKC - 1);
        if (!last) gemm_prefetch(sbase, (kc + 1) & 1, kc + 1, tid, m0, n0, Ah, Al, Bt);
        if (!last) CP_WAIT1(); else CP_WAIT0();
        __syncthreads();

        const int b = kc & 1;
        const uint32_t* AshW = (const uint32_t*)(dsm + b * BUFB);
        const uint32_t* AslW = (const uint32_t*)(dsm + b * BUFB + TILEB);
        const uint32_t* BsW  = (const uint32_t*)(dsm + b * BUFB + 2 * TILEB);

#pragma unroll
        for (int ks = 0; ks < 2; ks++) {
            const int c0w = ks * 8 + t;
            uint32_t bh[8][2];
#pragma unroll
            for (int ni = 0; ni < 8; ni++) {
                int n = wn * 64 + ni * 8 + g;
                bh[ni][0] = BsW[n * SPADW + c0w];
                bh[ni][1] = BsW[n * SPADW + c0w + 4];
            }
#pragma unroll
            for (int mi = 0; mi < 2; mi++) {
                int r = wm * 32 + mi * 16 + g;
                uint32_t ah[4], al[4];
                ah[0] = AshW[r * SPADW + c0w];
                ah[1] = AshW[(r + 8) * SPADW + c0w];
                ah[2] = AshW[r * SPADW + c0w + 4];
                ah[3] = AshW[(r + 8) * SPADW + c0w + 4];
                al[0] = AslW[r * SPADW + c0w];
                al[1] = AslW[(r + 8) * SPADW + c0w];
                al[2] = AslW[r * SPADW + c0w + 4];
                al[3] = AslW[(r + 8) * SPADW + c0w + 4];
#pragma unroll
                for (int ni = 0; ni < 8; ni++) {
                    mma16816h(acc[mi][ni], ah, bh[ni]);
                    mma16816h(acc[mi][ni], al, bh[ni]);
                }
            }
        }
        __syncthreads();
    }

#pragma unroll
    for (int mi = 0; mi < 2; mi++) {
        int r = m0 + wm * 32 + mi * 16 + g;
#pragma unroll
        for (int ni = 0; ni < 8; ni++) {
            int col = n0 + wn * 64 + ni * 8 + t * 2;
            float b0 = 0.f, b1 = 0.f;
            if (bias) { b0 = bias[col]; b1 = bias[col + 1]; }
            float2 v0, v1;
            v0.x = acc[mi][ni][0] + b0; v0.y = acc[mi][ni][1] + b1;
            v1.x = acc[mi][ni][2] + b0; v1.y = acc[mi][ni][3] + b1;
            *(float2*)&C[(size_t)r * QD + col] = v0;
            *(float2*)&C[(size_t)(r + 8) * QD + col] = v1;
        }
    }
}

// ---------------- Attention core (R8-proven): one CTA per (hw, head) -------
struct Boxes { int hs[TT]; int ws[TT]; int sub_h; int sub_w; };

__global__ __launch_bounds__(256)
void attn_kernel(const float* __restrict__ Q, const float* __restrict__ K,
                 const float* __restrict__ V, const float* __restrict__ RK,
                 const float* __restrict__ RV,
                 __half* __restrict__ ATH, __half* __restrict__ ATL,
                 Boxes bx) {
    const int hw = blockIdx.x;
    const int h  = blockIdx.y;
    const int tid = threadIdx.x;

    __shared__ float qs[TT][DH + 1];
    __shared__ float kst[DH][TT + 1];
    __shared__ float vs[TT][DH];
    __shared__ float rkt[DH][34];
    __shared__ float rvs[33][DH];
    __shared__ float sims[TT][TT + 1];

    const size_t base = ((size_t)hw * TT) * QD + h * DH;
#pragma unroll
    for (int e = tid; e < TT * DH; e += 256) {
        int t = e >> 6, d = e & 63;
        size_t gi = base + (size_t)t * QD + d;
        qs[t][d]  = Q[gi];
        kst[d][t] = K[gi];
        vs[t][d]  = V[gi];
    }
#pragma unroll
    for (int e = tid; e < 33 * DH; e += 256) {
        int r = e >> 6, d = e & 63;
        rkt[d][r] = RK[e];
        rvs[r][d] = RV[e];
    }
    __syncthreads();

    const int y = hw / 40, x = hw % 40;
    unsigned fg = 0;
#pragma unroll
    for (int t = 0; t < TT; t++) {
        int inb = (y >= bx.hs[t]) & (y < bx.hs[t] + bx.sub_h) &
                  (x >= bx.ws[t]) & (x < bx.ws[t] + bx.sub_w);
        fg |= (unsigned)inb << t;
    }

    {
        const int i = tid >> 4, j = tid & 15;
        const int r = j - i + 16;
        float s = 0.0f, sr = 0.0f;
#pragma unroll
        for (int d = 0; d < DH; d++) {
            float qv = qs[i][d];
            s  = fmaf(qv, kst[d][j], s);
            sr = fmaf(qv, rkt[d][r], sr);
        }
        float m = (((fg >> i) & 1u) == ((fg >> j) & 1u)) ? 1.0f : 0.01f;
        sims[i][j] = (s + sr) * SCALE * m;
    }
    __syncthreads();

    if (tid < TT) {
        float mx = -1e30f;
#pragma unroll
        for (int j = 0; j < TT; j++) mx = fmaxf(mx, sims[tid][j]);
        float sum = 0.0f;
#pragma unroll
        for (int j = 0; j < TT; j++) {
            float e = expf(sims[tid][j] - mx);
            sims[tid][j] = e;
            sum += e;
        }
        float inv = 1.0f / sum;
#pragma unroll
        for (int j = 0; j < TT; j++) sims[tid][j] *= inv;
    }
    __syncthreads();

#pragma unroll
    for (int e = tid; e < TT * DH; e += 256) {
        int i = e >> 6, d = e & 63;
        float o = 0.0f;
#pragma unroll
        for (int j = 0; j < TT; j++) {
            o = fmaf(sims[i][j], vs[j][d] + rvs[j - i + 16][d], o);
        }
        __half oh = __float2half(o);
        __half ol = __float2half(o - __half2float(oh));
        ATH[base + (size_t)i * QD + d] = oh;
        ATL[base + (size_t)i * QD + d] = ol;
    }
}

// ---------------------------- launcher -------------------------------------
extern "C" void kernel_launch(void* const* d_in, const int* in_sizes, int n_in,
                              void* d_out, int out_size) {
    const float* x     = (const float*)d_in[0];
    const float* Wq    = (const float*)d_in[1];
    const float* Wk    = (const float*)d_in[2];
    const float* Wv    = (const float*)d_in[3];
    const float* Wo    = (const float*)d_in[4];
    const float* bo    = (const float*)d_in[5];
    const float* rel_k = (const float*)d_in[6];
    const float* rel_v = (const float*)d_in[7];
    float* out = (float*)d_out;

    float *q, *k, *v;
    __half *xh, *xl, *ath, *atl, *wt;
    cudaGetSymbolAddress((void**)&q,   g_q);
    cudaGetSymbolAddress((void**)&k,   g_k);
    cudaGetSymbolAddress((void**)&v,   g_v);
    cudaGetSymbolAddress((void**)&xh,  g_xh);
    cudaGetSymbolAddress((void**)&xl,  g_xl);
    cudaGetSymbolAddress((void**)&ath, g_ath);
    cudaGetSymbolAddress((void**)&atl, g_atl);
    cudaGetSymbolAddress((void**)&wt,  g_wt);

    // Box path (exact binary64 semantics): SUB_H=15, SUB_W=9
    Boxes bx;
    bx.sub_h = (int)((0.35 - 0.10) * 64.0);
    bx.sub_w = (int)((0.35 - 0.10) * 40.0);
    for (int t = 0; t < TT; t++) {
        double r  = (double)t / 15.0;
        double h0 = 0.10 + r * (0.60 - 0.10);
        double w0 = 0.10 + r * (0.60 - 0.10);
        bx.hs[t] = (int)(h0 * 64.0);
        bx.ws[t] = (int)(w0 * 40.0);
    }

    cudaFuncSetAttribute(gemm_h, cudaFuncAttributeMaxDynamicSharedMemorySize, GDYN);

    split_x<<<MTOT * QD / 512, 256>>>(x, xh, xl);
    split_w<<<dim3(16, 16, 4), dim3(32, 8)>>>(Wq, Wk, Wv, Wo, wt);

    // fused QKV: z selects weight & output
    gemm_h<<<dim3(4, 320, 3), 256, GDYN>>>(xh, xl, wt, nullptr, q, k, v);

    attn_kernel<<<dim3(HW, HEADS), 256>>>(q, k, v, rel_k, rel_v, ath, atl, bx);

    // output projection: weight index 3 (pre-offset), + bias
    gemm_h<<<dim3(4, 320, 1), 256, GDYN>>>(ath, atl,
                                           wt + (size_t)3 * QD * QD,
                                           bo, out, out, out);
}

// round 13
// speedup vs baseline: 1.6193x; 1.0426x over previous
#include <cuda_runtime.h>
#include <cuda_fp16.h>
#include <math.h>
#include <stdint.h>

#define HW    2560
#define TT    16
#define HEADS 8
#define DH    64
#define QD    512
#define MTOT  (HW * TT)      // 40960
#define SCALE 0.125f

// ---------------- scratch (device globals: allocation-free) ----------------
__device__ float g_q[(size_t)MTOT * QD];
__device__ float g_k[(size_t)MTOT * QD];
__device__ float g_v[(size_t)MTOT * QD];
__device__ __half g_xh[(size_t)MTOT * QD];
__device__ __half g_xl[(size_t)MTOT * QD];
__device__ __half g_ath[(size_t)MTOT * QD];
__device__ __half g_atl[(size_t)MTOT * QD];
__device__ __half g_wt[(size_t)4 * QD * QD];    // Wt[w][n][k] fp16

// ---------------- helpers --------------------------------------------------
__device__ __forceinline__ uint32_t smem_u32(const void* p) {
    uint32_t a;
    asm("{ .reg .u64 t; cvta.to.shared.u64 t, %1; cvt.u32.u64 %0, t; }" : "=r"(a) : "l"(p));
    return a;
}
__device__ __forceinline__ void mma16816h(float* d, const uint32_t* a, const uint32_t* b) {
    asm volatile(
        "mma.sync.aligned.m16n8k16.row.col.f32.f16.f16.f32 "
        "{%0,%1,%2,%3}, {%4,%5,%6,%7}, {%8,%9}, {%0,%1,%2,%3};"
        : "+f"(d[0]), "+f"(d[1]), "+f"(d[2]), "+f"(d[3])
        : "r"(a[0]), "r"(a[1]), "r"(a[2]), "r"(a[3]), "r"(b[0]), "r"(b[1]));
}
__device__ __forceinline__ void cp16(uint32_t dst, const void* src) {
    asm volatile("cp.async.ca.shared.global [%0], [%1], 16;" :: "r"(dst), "l"(src));
}
#define CP_COMMIT() asm volatile("cp.async.commit_group;" ::: "memory")
#define CP_WAIT1()  asm volatile("cp.async.wait_group 1;" ::: "memory")
#define CP_WAIT0()  asm volatile("cp.async.wait_group 0;" ::: "memory")

// ---------------- split passes ---------------------------------------------
__global__ __launch_bounds__(256)
void split_x(const float* __restrict__ X, __half* __restrict__ xh,
             __half* __restrict__ xl) {
    size_t i = (size_t)blockIdx.x * 256 + threadIdx.x;
    float2 a = ((const float2*)X)[i];
    __half hx = __float2half(a.x);
    __half hy = __float2half(a.y);
    __half lx = __float2half(a.x - __half2float(hx));
    __half ly = __float2half(a.y - __half2float(hy));
    ((__half2*)xh)[i] = __halves2half2(hx, hy);
    ((__half2*)xl)[i] = __halves2half2(lx, ly);
}

// transpose the 4 weight matrices to fp16: Wt[w][n][k] = fp16(W[k][n])
__global__ __launch_bounds__(256)
void split_w(const float* __restrict__ W0, const float* __restrict__ W1,
             const float* __restrict__ W2, const float* __restrict__ W3,
             __half* __restrict__ wt) {
    __shared__ float t[32][33];
    const int w = blockIdx.z;
    const float* W = (w == 0) ? W0 : (w == 1) ? W1 : (w == 2) ? W2 : W3;
    const int tx = threadIdx.x, ty = threadIdx.y;
#pragma unroll
    for (int i = 0; i < 4; i++)
        t[ty + 8 * i][tx] = W[(size_t)(blockIdx.y * 32 + ty + 8 * i) * QD + blockIdx.x * 32 + tx];
    __syncthreads();
#pragma unroll
    for (int i = 0; i < 4; i++) {
        int n = blockIdx.x * 32 + ty + 8 * i;
        int k = blockIdx.y * 32 + tx;
        wt[((size_t)w * QD + n) * QD + k] = __float2half(t[tx][ty + 8 * i]);
    }
}

// ======== fp16 2-term GEMM: C = (Ah+Al) @ B, fp32 accum ====================
#define BKC   32
#define SPADW 20                    // row stride in words (40 fp16)
#define TILEB (128 * 80)            // 10240 B per tile
#define BUFB  (3 * TILEB)           // 30720 B per stage
#define GDYN  (2 * BUFB)            // 61440 B

__device__ __forceinline__ void gemm_prefetch(
    uint32_t sbase, int b, int kc, int tid, int m0, int n0,
    const __half* Ah, const __half* Al, const __half* Bt) {
#pragma unroll
    for (int i = 0; i < 6; i++) {
        int e = tid + i * 256;
        int tile = e >> 9;
        int r    = (e >> 2) & 127;
        int c16  = e & 3;
        uint32_t dst = sbase + b * BUFB + tile * TILEB + r * 80 + c16 * 16;
        const __half* src;
        if (tile == 0)      src = Ah + (size_t)(m0 + r) * QD + kc * BKC + c16 * 8;
        else if (tile == 1) src = Al + (size_t)(m0 + r) * QD + kc * BKC + c16 * 8;
        else                src = Bt + (size_t)(n0 + r) * QD + kc * BKC + c16 * 8;
        cp16(dst, src);
    }
    CP_COMMIT();
}

__global__ __launch_bounds__(256, 2)
void gemm_h(const __half* __restrict__ Ah, const __half* __restrict__ Al,
            const __half* __restrict__ Wt, const float* __restrict__ bias,
            float* __restrict__ C0, float* __restrict__ C1, float* __restrict__ C2) {
    extern __shared__ char dsm[];
    const uint32_t sbase = smem_u32(dsm);

    const int tid = threadIdx.x;
    const int wid = tid >> 5, lid = tid & 31;
    const int wm = wid & 3, wn = wid >> 2;      // 4(m) x 2(n)
    const int g = lid >> 2, t = lid & 3;
    const int m0 = blockIdx.y * 128;
    const int n0 = blockIdx.x * 128;
    const int w  = blockIdx.z;
    float* C = (w == 0) ? C0 : (w == 1) ? C1 : C2;
    const __half* Bt = Wt + (size_t)w * QD * QD;

    float acc[2][8][4];
#pragma unroll
    for (int mi = 0; mi < 2; mi++)
#pragma unroll
        for (int ni = 0; ni < 8; ni++)
#pragma unroll
            for (int c = 0; c < 4; c++) acc[mi][ni][c] = 0.0f;

    gemm_prefetch(sbase, 0, 0, tid, m0, n0, Ah, Al, Bt);

    for (int kc = 0; kc < QD / BKC; kc++) {
        const int last = (kc == QD / BKC - 1);
        if (!last) gemm_prefetch(sbase, (kc + 1) & 1, kc + 1, tid, m0, n0, Ah, Al, Bt);
        if (!last) CP_WAIT1(); else CP_WAIT0();
        __syncthreads();

        const int b = kc & 1;
        const uint32_t* AshW = (const uint32_t*)(dsm + b * BUFB);
        const uint32_t* AslW = (const uint32_t*)(dsm + b * BUFB + TILEB);
        const uint32_t* BsW  = (const uint32_t*)(dsm + b * BUFB + 2 * TILEB);

#pragma unroll
        for (int ks = 0; ks < 2; ks++) {
            const int c0w = ks * 8 + t;
            uint32_t bh[8][2];
#pragma unroll
            for (int ni = 0; ni < 8; ni++) {
                int n = wn * 64 + ni * 8 + g;
                bh[ni][0] = BsW[n * SPADW + c0w];
                bh[ni][1] = BsW[n * SPADW + c0w + 4];
            }
#pragma unroll
            for (int mi = 0; mi < 2; mi++) {
                int r = wm * 32 + mi * 16 + g;
                uint32_t ah[4], al[4];
                ah[0] = AshW[r * SPADW + c0w];
                ah[1] = AshW[(r + 8) * SPADW + c0w];
                ah[2] = AshW[r * SPADW + c0w + 4];
                ah[3] = AshW[(r + 8) * SPADW + c0w + 4];
                al[0] = AslW[r * SPADW + c0w];
                al[1] = AslW[(r + 8) * SPADW + c0w];
                al[2] = AslW[r * SPADW + c0w + 4];
                al[3] = AslW[(r + 8) * SPADW + c0w + 4];
#pragma unroll
                for (int ni = 0; ni < 8; ni++) {
                    mma16816h(acc[mi][ni], ah, bh[ni]);
                    mma16816h(acc[mi][ni], al, bh[ni]);
                }
            }
        }
        __syncthreads();
    }

#pragma unroll
    for (int mi = 0; mi < 2; mi++) {
        int r = m0 + wm * 32 + mi * 16 + g;
#pragma unroll
        for (int ni = 0; ni < 8; ni++) {
            int col = n0 + wn * 64 + ni * 8 + t * 2;
            float b0 = 0.f, b1 = 0.f;
            if (bias) { b0 = bias[col]; b1 = bias[col + 1]; }
            float2 v0, v1;
            v0.x = acc[mi][ni][0] + b0; v0.y = acc[mi][ni][1] + b1;
            v1.x = acc[mi][ni][2] + b0; v1.y = acc[mi][ni][3] + b1;
            *(float2*)&C[(size_t)r * QD + col] = v0;
            *(float2*)&C[(size_t)(r + 8) * QD + col] = v1;
        }
    }
}

// ---------------- Attention v4: float4 smem layout, pad 68 -----------------
// All tiles row-major with 68-float row stride. 16-B segment index =
// row*17 + d4; 17 odd => 16 consecutive rows spread over all 8
// segment-groups (2-cycle wavefronts for 16-row gathers).
struct Boxes { int hs[TT]; int ws[TT]; int sub_h; int sub_w; };

#define PADF 68

__global__ __launch_bounds__(256)
void attn_kernel(const float* __restrict__ Q, const float* __restrict__ K,
                 const float* __restrict__ V, const float* __restrict__ RK,
                 const float* __restrict__ RV,
                 __half* __restrict__ ATH, __half* __restrict__ ATL,
                 Boxes bx) {
    const int hw = blockIdx.x;
    const int h  = blockIdx.y;
    const int tid = threadIdx.x;

    __shared__ float qs[TT * PADF];
    __shared__ float ks[TT * PADF];
    __shared__ float vs[TT * PADF];
    __shared__ float rks[33 * PADF];
    __shared__ float rvs[33 * PADF];
    __shared__ float sims[TT][TT + 1];

    const size_t base = ((size_t)hw * TT) * QD + h * DH;
#pragma unroll
    for (int e = tid; e < TT * DH; e += 256) {
        int t = e >> 6, d = e & 63;
        size_t gi = base + (size_t)t * QD + d;
        qs[t * PADF + d] = Q[gi];
        ks[t * PADF + d] = K[gi];
        vs[t * PADF + d] = V[gi];
    }
#pragma unroll
    for (int e = tid; e < 33 * DH; e += 256) {
        int r = e >> 6, d = e & 63;
        rks[r * PADF + d] = RK[e];
        rvs[r * PADF + d] = RV[e];
    }
    __syncthreads();

    const int y = hw / 40, x = hw % 40;
    unsigned fg = 0;
#pragma unroll
    for (int t = 0; t < TT; t++) {
        int inb = (y >= bx.hs[t]) & (y < bx.hs[t] + bx.sub_h) &
                  (x >= bx.ws[t]) & (x < bx.ws[t] + bx.sub_w);
        fg |= (unsigned)inb << t;
    }

    // ---- sim: one (i,j) per thread, float4 dot ----
    {
        const int i = tid >> 4, j = tid & 15;
        const int r = j - i + 16;
        float s = 0.0f, sr = 0.0f;
#pragma unroll
        for (int d4 = 0; d4 < 16; d4++) {
            float4 qv = *(const float4*)&qs[i * PADF + d4 * 4];
            float4 kv = *(const float4*)&ks[j * PADF + d4 * 4];
            float4 rv = *(const float4*)&rks[r * PADF + d4 * 4];
            s  = fmaf(qv.x, kv.x, s);  s  = fmaf(qv.y, kv.y, s);
            s  = fmaf(qv.z, kv.z, s);  s  = fmaf(qv.w, kv.w, s);
            sr = fmaf(qv.x, rv.x, sr); sr = fmaf(qv.y, rv.y, sr);
            sr = fmaf(qv.z, rv.z, sr); sr = fmaf(qv.w, rv.w, sr);
        }
        float m = (((fg >> i) & 1u) == ((fg >> j) & 1u)) ? 1.0f : 0.01f;
        sims[i][j] = (s + sr) * SCALE * m;
    }
    __syncthreads();

    if (tid < TT) {
        float mx = -1e30f;
#pragma unroll
        for (int j = 0; j < TT; j++) mx = fmaxf(mx, sims[tid][j]);
        float sum = 0.0f;
#pragma unroll
        for (int j = 0; j < TT; j++) {
            float e = expf(sims[tid][j] - mx);
            sims[tid][j] = e;
            sum += e;
        }
        float inv = 1.0f / sum;
#pragma unroll
        for (int j = 0; j < TT; j++) sims[tid][j] *= inv;
    }
    __syncthreads();

    // ---- out: one (i, d4) float4 per thread ----
    {
        const int i = tid >> 4, d4 = tid & 15;
        float4 o = make_float4(0.f, 0.f, 0.f, 0.f);
#pragma unroll
        for (int j = 0; j < TT; j++) {
            float s = sims[i][j];
            float4 v  = *(const float4*)&vs[j * PADF + d4 * 4];
            float4 rv = *(const float4*)&rvs[(j - i + 16) * PADF + d4 * 4];
            o.x = fmaf(s, v.x + rv.x, o.x);
            o.y = fmaf(s, v.y + rv.y, o.y);
            o.z = fmaf(s, v.z + rv.z, o.z);
            o.w = fmaf(s, v.w + rv.w, o.w);
        }
        size_t ob = base + (size_t)i * QD + d4 * 4;
        __half h0 = __float2half(o.x), h1 = __float2half(o.y);
        __half h2 = __float2half(o.z), h3 = __float2half(o.w);
        __half l0 = __float2half(o.x - __half2float(h0));
        __half l1 = __float2half(o.y - __half2float(h1));
        __half l2 = __float2half(o.z - __half2float(h2));
        __half l3 = __float2half(o.w - __half2float(h3));
        *(__half2*)&ATH[ob]     = __halves2half2(h0, h1);
        *(__half2*)&ATH[ob + 2] = __halves2half2(h2, h3);
        *(__half2*)&ATL[ob]     = __halves2half2(l0, l1);
        *(__half2*)&ATL[ob + 2] = __halves2half2(l2, l3);
    }
}

// ---------------------------- launcher -------------------------------------
extern "C" void kernel_launch(void* const* d_in, const int* in_sizes, int n_in,
                              void* d_out, int out_size) {
    const float* x     = (const float*)d_in[0];
    const float* Wq    = (const float*)d_in[1];
    const float* Wk    = (const float*)d_in[2];
    const float* Wv    = (const float*)d_in[3];
    const float* Wo    = (const float*)d_in[4];
    const float* bo    = (const float*)d_in[5];
    const float* rel_k = (const float*)d_in[6];
    const float* rel_v = (const float*)d_in[7];
    float* out = (float*)d_out;

    float *q, *k, *v;
    __half *xh, *xl, *ath, *atl, *wt;
    cudaGetSymbolAddress((void**)&q,   g_q);
    cudaGetSymbolAddress((void**)&k,   g_k);
    cudaGetSymbolAddress((void**)&v,   g_v);
    cudaGetSymbolAddress((void**)&xh,  g_xh);
    cudaGetSymbolAddress((void**)&xl,  g_xl);
    cudaGetSymbolAddress((void**)&ath, g_ath);
    cudaGetSymbolAddress((void**)&atl, g_atl);
    cudaGetSymbolAddress((void**)&wt,  g_wt);

    // Box path (exact binary64 semantics): SUB_H=15, SUB_W=9
    Boxes bx;
    bx.sub_h = (int)((0.35 - 0.10) * 64.0);
    bx.sub_w = (int)((0.35 - 0.10) * 40.0);
    for (int t = 0; t < TT; t++) {
        double r  = (double)t / 15.0;
        double h0 = 0.10 + r * (0.60 - 0.10);
        double w0 = 0.10 + r * (0.60 - 0.10);
        bx.hs[t] = (int)(h0 * 64.0);
        bx.ws[t] = (int)(w0 * 40.0);
    }

    cudaFuncSetAttribute(gemm_h, cudaFuncAttributeMaxDynamicSharedMemorySize, GDYN);

    split_x<<<MTOT * QD / 512, 256>>>(x, xh, xl);
    split_w<<<dim3(16, 16, 4), dim3(32, 8)>>>(Wq, Wk, Wv, Wo, wt);

    gemm_h<<<dim3(4, 320, 3), 256, GDYN>>>(xh, xl, wt, nullptr, q, k, v);

    attn_kernel<<<dim3(HW, HEADS), 256>>>(q, k, v, rel_k, rel_v, ath, atl, bx);

    gemm_h<<<dim3(4, 320, 1), 256, GDYN>>>(ath, atl,
                                           wt + (size_t)3 * QD * QD,
                                           bo, out, out, out);
}

// round 15
// speedup vs baseline: 2.1524x; 1.3293x over previous
#include <cuda_runtime.h>
#include <cuda_fp16.h>
#include <math.h>
#include <stdint.h>

#define HW    2560
#define TT    16
#define HEADS 8
#define DH    64
#define QD    512
#define MTOT  (HW * TT)      // 40960
#define SCALE 0.125f

// ---------------- scratch (device globals: allocation-free) ----------------
__device__ float g_q[(size_t)MTOT * QD];
__device__ float g_k[(size_t)MTOT * QD];
__device__ float g_v[(size_t)MTOT * QD];
__device__ __half g_xh[(size_t)MTOT * QD];
__device__ __half g_ath[(size_t)MTOT * QD];
__device__ __half g_wt[(size_t)4 * QD * QD];    // Wt[w][n][k] fp16

// ---------------- helpers --------------------------------------------------
__device__ __forceinline__ uint32_t smem_u32(const void* p) {
    uint32_t a;
    asm("{ .reg .u64 t; cvta.to.shared.u64 t, %1; cvt.u32.u64 %0, t; }" : "=r"(a) : "l"(p));
    return a;
}
__device__ __forceinline__ void mma16816h(float* d, const uint32_t* a, const uint32_t* b) {
    asm volatile(
        "mma.sync.aligned.m16n8k16.row.col.f32.f16.f16.f32 "
        "{%0,%1,%2,%3}, {%4,%5,%6,%7}, {%8,%9}, {%0,%1,%2,%3};"
        : "+f"(d[0]), "+f"(d[1]), "+f"(d[2]), "+f"(d[3])
        : "r"(a[0]), "r"(a[1]), "r"(a[2]), "r"(a[3]), "r"(b[0]), "r"(b[1]));
}
__device__ __forceinline__ void cp16(uint32_t dst, const void* src) {
    asm volatile("cp.async.ca.shared.global [%0], [%1], 16;" :: "r"(dst), "l"(src));
}
#define CP_COMMIT() asm volatile("cp.async.commit_group;" ::: "memory")
#define CP_WAIT1()  asm volatile("cp.async.wait_group 1;" ::: "memory")
#define CP_WAIT0()  asm volatile("cp.async.wait_group 0;" ::: "memory")

// ---------------- conversion passes ----------------------------------------
__global__ __launch_bounds__(256)
void conv_x(const float* __restrict__ X, __half* __restrict__ xh) {
    size_t i = (size_t)blockIdx.x * 256 + threadIdx.x;
    float2 a = ((const float2*)X)[i];
    ((__half2*)xh)[i] = __halves2half2(__float2half(a.x), __float2half(a.y));
}

// transpose the 4 weight matrices to fp16: Wt[w][n][k] = fp16(W[k][n])
__global__ __launch_bounds__(256)
void conv_w(const float* __restrict__ W0, const float* __restrict__ W1,
            const float* __restrict__ W2, const float* __restrict__ W3,
            __half* __restrict__ wt) {
    __shared__ float t[32][33];
    const int w = blockIdx.z;
    const float* W = (w == 0) ? W0 : (w == 1) ? W1 : (w == 2) ? W2 : W3;
    const int tx = threadIdx.x, ty = threadIdx.y;
#pragma unroll
    for (int i = 0; i < 4; i++)
        t[ty + 8 * i][tx] = W[(size_t)(blockIdx.y * 32 + ty + 8 * i) * QD + blockIdx.x * 32 + tx];
    __syncthreads();
#pragma unroll
    for (int i = 0; i < 4; i++) {
        int n = blockIdx.x * 32 + ty + 8 * i;
        int k = blockIdx.y * 32 + tx;
        wt[((size_t)w * QD + n) * QD + k] = __float2half(t[tx][ty + 8 * i]);
    }
}

// ======== fp16 GEMM: C[M,512] = A @ W^T, fp32 accum ========================
// CTA 128x128, BK=32, 256 thr, 4(m)x2(n) warps, 32x64 warp tiles.
// 2 smem tiles per stage (A, B), double buffered via cp.async.
#define BKC   32
#define SPADW 20                    // row stride in words (40 fp16)
#define TILEB (128 * 80)            // 10240 B per tile
#define BUFB  (2 * TILEB)           // 20480 B per stage
#define GDYN  (2 * BUFB)            // 40960 B

__device__ __forceinline__ void gemm_prefetch(
    uint32_t sbase, int b, int kc, int tid, int m0, int n0,
    const __half* Ah, const __half* Bt) {
#pragma unroll
    for (int i = 0; i < 4; i++) {
        int e = tid + i * 256;
        int tile = e >> 9;
        int r    = (e >> 2) & 127;
        int c16  = e & 3;
        uint32_t dst = sbase + b * BUFB + tile * TILEB + r * 80 + c16 * 16;
        const __half* src = (tile == 0)
            ? Ah + (size_t)(m0 + r) * QD + kc * BKC + c16 * 8
            : Bt + (size_t)(n0 + r) * QD + kc * BKC + c16 * 8;
        cp16(dst, src);
    }
    CP_COMMIT();
}

// z selects weight w and output C; bias != nullptr -> add bias.
__global__ __launch_bounds__(256, 2)
void gemm_h(const __half* __restrict__ Ah, const __half* __restrict__ Wt,
            const float* __restrict__ bias,
            float* __restrict__ C0, float* __restrict__ C1, float* __restrict__ C2) {
    extern __shared__ char dsm[];
    const uint32_t sbase = smem_u32(dsm);

    const int tid = threadIdx.x;
    const int wid = tid >> 5, lid = tid & 31;
    const int wm = wid & 3, wn = wid >> 2;      // 4(m) x 2(n)
    const int g = lid >> 2, t = lid & 3;
    const int m0 = blockIdx.y * 128;
    const int n0 = blockIdx.x * 128;
    const int w  = blockIdx.z;
    float* C = (w == 0) ? C0 : (w == 1) ? C1 : C2;
    const __half* Bt = Wt + (size_t)w * QD * QD;

    float acc[2][8][4];
#pragma unroll
    for (int mi = 0; mi < 2; mi++)
#pragma unroll
        for (int ni = 0; ni < 8; ni++)
#pragma unroll
            for (int c = 0; c < 4; c++) acc[mi][ni][c] = 0.0f;

    gemm_prefetch(sbase, 0, 0, tid, m0, n0, Ah, Bt);

    for (int kc = 0; kc < QD / BKC; kc++) {
        const int last = (kc == QD / BKC - 1);
        if (!last) gemm_prefetch(sbase, (kc + 1) & 1, kc + 1, tid, m0, n0, Ah, Bt);
        if (!last) CP_WAIT1(); else CP_WAIT0();
        __syncthreads();

        const int b = kc & 1;
        const uint32_t* AsW = (const uint32_t*)(dsm + b * BUFB);
        const uint32_t* BsW = (const uint32_t*)(dsm + b * BUFB + TILEB);

#pragma unroll
        for (int ks = 0; ks < 2; ks++) {
            const int c0w = ks * 8 + t;
            uint32_t bh[8][2];
#pragma unroll
            for (int ni = 0; ni < 8; ni++) {
                int n = wn * 64 + ni * 8 + g;
                bh[ni][0] = BsW[n * SPADW + c0w];
                bh[ni][1] = BsW[n * SPADW + c0w + 4];
            }
#pragma unroll
            for (int mi = 0; mi < 2; mi++) {
                int r = wm * 32 + mi * 16 + g;
                uint32_t ah[4];
                ah[0] = AsW[r * SPADW + c0w];
                ah[1] = AsW[(r + 8) * SPADW + c0w];
                ah[2] = AsW[r * SPADW + c0w + 4];
                ah[3] = AsW[(r + 8) * SPADW + c0w + 4];
#pragma unroll
                for (int ni = 0; ni < 8; ni++)
                    mma16816h(acc[mi][ni], ah, bh[ni]);
            }
        }
        __syncthreads();
    }

#pragma unroll
    for (int mi = 0; mi < 2; mi++) {
        int r = m0 + wm * 32 + mi * 16 + g;
#pragma unroll
        for (int ni = 0; ni < 8; ni++) {
            int col = n0 + wn * 64 + ni * 8 + t * 2;
            float b0 = 0.f, b1 = 0.f;
            if (bias) { b0 = bias[col]; b1 = bias[col + 1]; }
            float2 v0, v1;
            v0.x = acc[mi][ni][0] + b0; v0.y = acc[mi][ni][1] + b1;
            v1.x = acc[mi][ni][2] + b0; v1.y = acc[mi][ni][3] + b1;
            *(float2*)&C[(size_t)r * QD + col] = v0;
            *(float2*)&C[(size_t)(r + 8) * QD + col] = v1;
        }
    }
}

// ---------------- Attention v4: float4 smem layout, pad 68 -----------------
struct Boxes { int hs[TT]; int ws[TT]; int sub_h; int sub_w; };

#define PADF 68

__global__ __launch_bounds__(256)
void attn_kernel(const float* __restrict__ Q, const float* __restrict__ K,
                 const float* __restrict__ V, const float* __restrict__ RK,
                 const float* __restrict__ RV,
                 __half* __restrict__ ATH, Boxes bx) {
    const int hw = blockIdx.x;
    const int h  = blockIdx.y;
    const int tid = threadIdx.x;

    __shared__ float qs[TT * PADF];
    __shared__ float ks[TT * PADF];
    __shared__ float vs[TT * PADF];
    __shared__ float rks[33 * PADF];
    __shared__ float rvs[33 * PADF];
    __shared__ float sims[TT][TT + 1];

    const size_t base = ((size_t)hw * TT) * QD + h * DH;
#pragma unroll
    for (int e = tid; e < TT * DH; e += 256) {
        int t = e >> 6, d = e & 63;
        size_t gi = base + (size_t)t * QD + d;
        qs[t * PADF + d] = Q[gi];
        ks[t * PADF + d] = K[gi];
        vs[t * PADF + d] = V[gi];
    }
#pragma unroll
    for (int e = tid; e < 33 * DH; e += 256) {
        int r = e >> 6, d = e & 63;
        rks[r * PADF + d] = RK[e];
        rvs[r * PADF + d] = RV[e];
    }
    __syncthreads();

    const int y = hw / 40, x = hw % 40;
    unsigned fg = 0;
#pragma unroll
    for (int t = 0; t < TT; t++) {
        int inb = (y >= bx.hs[t]) & (y < bx.hs[t] + bx.sub_h) &
                  (x >= bx.ws[t]) & (x < bx.ws[t] + bx.sub_w);
        fg |= (unsigned)inb << t;
    }

    // ---- sim: one (i,j) per thread, float4 dot ----
    {
        const int i = tid >> 4, j = tid & 15;
        const int r = j - i + 16;
        float s = 0.0f, sr = 0.0f;
#pragma unroll
        for (int d4 = 0; d4 < 16; d4++) {
            float4 qv = *(const float4*)&qs[i * PADF + d4 * 4];
            float4 kv = *(const float4*)&ks[j * PADF + d4 * 4];
            float4 rv = *(const float4*)&rks[r * PADF + d4 * 4];
            s  = fmaf(qv.x, kv.x, s);  s  = fmaf(qv.y, kv.y, s);
            s  = fmaf(qv.z, kv.z, s);  s  = fmaf(qv.w, kv.w, s);
            sr = fmaf(qv.x, rv.x, sr); sr = fmaf(qv.y, rv.y, sr);
            sr = fmaf(qv.z, rv.z, sr); sr = fmaf(qv.w, rv.w, sr);
        }
        float m = (((fg >> i) & 1u) == ((fg >> j) & 1u)) ? 1.0f : 0.01f;
        sims[i][j] = (s + sr) * SCALE * m;
    }
    __syncthreads();

    if (tid < TT) {
        float mx = -1e30f;
#pragma unroll
        for (int j = 0; j < TT; j++) mx = fmaxf(mx, sims[tid][j]);
        float sum = 0.0f;
#pragma unroll
        for (int j = 0; j < TT; j++) {
            float e = expf(sims[tid][j] - mx);
            sims[tid][j] = e;
            sum += e;
        }
        float inv = 1.0f / sum;
#pragma unroll
        for (int j = 0; j < TT; j++) sims[tid][j] *= inv;
    }
    __syncthreads();

    // ---- out: one (i, d4) float4 per thread, emit fp16 ----
    {
        const int i = tid >> 4, d4 = tid & 15;
        float4 o = make_float4(0.f, 0.f, 0.f, 0.f);
#pragma unroll
        for (int j = 0; j < TT; j++) {
            float s = sims[i][j];
            float4 v  = *(const float4*)&vs[j * PADF + d4 * 4];
            float4 rv = *(const float4*)&rvs[(j - i + 16) * PADF + d4 * 4];
            o.x = fmaf(s, v.x + rv.x, o.x);
            o.y = fmaf(s, v.y + rv.y, o.y);
            o.z = fmaf(s, v.z + rv.z, o.z);
            o.w = fmaf(s, v.w + rv.w, o.w);
        }
        size_t ob = base + (size_t)i * QD + d4 * 4;
        *(__half2*)&ATH[ob]     = __halves2half2(__float2half(o.x), __float2half(o.y));
        *(__half2*)&ATH[ob + 2] = __halves2half2(__float2half(o.z), __float2half(o.w));
    }
}

// ---------------------------- launcher -------------------------------------
extern "C" void kernel_launch(void* const* d_in, const int* in_sizes, int n_in,
                              void* d_out, int out_size) {
    const float* x     = (const float*)d_in[0];
    const float* Wq    = (const float*)d_in[1];
    const float* Wk    = (const float*)d_in[2];
    const float* Wv    = (const float*)d_in[3];
    const float* Wo    = (const float*)d_in[4];
    const float* bo    = (const float*)d_in[5];
    const float* rel_k = (const float*)d_in[6];
    const float* rel_v = (const float*)d_in[7];
    float* out = (float*)d_out;

    float *q, *k, *v;
    __half *xh, *ath, *wt;
    cudaGetSymbolAddress((void**)&q,   g_q);
    cudaGetSymbolAddress((void**)&k,   g_k);
    cudaGetSymbolAddress((void**)&v,   g_v);
    cudaGetSymbolAddress((void**)&xh,  g_xh);
    cudaGetSymbolAddress((void**)&ath, g_ath);
    cudaGetSymbolAddress((void**)&wt,  g_wt);

    // Box path (exact binary64 semantics): SUB_H=15, SUB_W=9
    Boxes bx;
    bx.sub_h = (int)((0.35 - 0.10) * 64.0);
    bx.sub_w = (int)((0.35 - 0.10) * 40.0);
    for (int t = 0; t < TT; t++) {
        double r  = (double)t / 15.0;
        double h0 = 0.10 + r * (0.60 - 0.10);
        double w0 = 0.10 + r * (0.60 - 0.10);
        bx.hs[t] = (int)(h0 * 64.0);
        bx.ws[t] = (int)(w0 * 40.0);
    }

    cudaFuncSetAttribute(gemm_h, cudaFuncAttributeMaxDynamicSharedMemorySize, GDYN);

    conv_x<<<MTOT * QD / 512, 256>>>(x, xh);
    conv_w<<<dim3(16, 16, 4), dim3(32, 8)>>>(Wq, Wk, Wv, Wo, wt);

    // fused QKV: z selects weight & output
    gemm_h<<<dim3(4, 320, 3), 256, GDYN>>>(xh, wt, nullptr, q, k, v);

    attn_kernel<<<dim3(HW, HEADS), 256>>>(q, k, v, rel_k, rel_v, ath, bx);

    // output projection: weight index 3 (pre-offset), + bias
    gemm_h<<<dim3(4, 320, 1), 256, GDYN>>>(ath, wt + (size_t)3 * QD * QD,
                                           bo, out, out, out);
}

// round 16
// speedup vs baseline: 2.2965x; 1.0670x over previous
#include <cuda_runtime.h>
#include <cuda_fp16.h>
#include <math.h>
#include <stdint.h>

#define HW    2560
#define TT    16
#define HEADS 8
#define DH    64
#define QD    512
#define MTOT  (HW * TT)      // 40960
#define SCALE 0.125f

// ---------------- scratch (device globals: allocation-free) ----------------
__device__ __half g_qh[(size_t)MTOT * QD];
__device__ __half g_kh[(size_t)MTOT * QD];
__device__ __half g_vh[(size_t)MTOT * QD];
__device__ __half g_xh[(size_t)MTOT * QD];
__device__ __half g_ath[(size_t)MTOT * QD];
__device__ __half g_wt[(size_t)4 * QD * QD];    // Wt[w][n][k] fp16

// ---------------- helpers --------------------------------------------------
__device__ __forceinline__ uint32_t smem_u32(const void* p) {
    uint32_t a;
    asm("{ .reg .u64 t; cvta.to.shared.u64 t, %1; cvt.u32.u64 %0, t; }" : "=r"(a) : "l"(p));
    return a;
}
__device__ __forceinline__ void mma16816h(float* d, const uint32_t* a, const uint32_t* b) {
    asm volatile(
        "mma.sync.aligned.m16n8k16.row.col.f32.f16.f16.f32 "
        "{%0,%1,%2,%3}, {%4,%5,%6,%7}, {%8,%9}, {%0,%1,%2,%3};"
        : "+f"(d[0]), "+f"(d[1]), "+f"(d[2]), "+f"(d[3])
        : "r"(a[0]), "r"(a[1]), "r"(a[2]), "r"(a[3]), "r"(b[0]), "r"(b[1]));
}
__device__ __forceinline__ void cp16(uint32_t dst, const void* src) {
    asm volatile("cp.async.ca.shared.global [%0], [%1], 16;" :: "r"(dst), "l"(src));
}
#define CP_COMMIT() asm volatile("cp.async.commit_group;" ::: "memory")
#define CP_WAIT2()  asm volatile("cp.async.wait_group 2;" ::: "memory")
#define CP_WAIT0()  asm volatile("cp.async.wait_group 0;" ::: "memory")

// ---------------- conversion passes ----------------------------------------
__global__ __launch_bounds__(256)
void conv_x(const float* __restrict__ X, __half* __restrict__ xh) {
    size_t i = (size_t)blockIdx.x * 256 + threadIdx.x;
    float2 a = ((const float2*)X)[i];
    ((__half2*)xh)[i] = __halves2half2(__float2half(a.x), __float2half(a.y));
}

__global__ __launch_bounds__(256)
void conv_w(const float* __restrict__ W0, const float* __restrict__ W1,
            const float* __restrict__ W2, const float* __restrict__ W3,
            __half* __restrict__ wt) {
    __shared__ float t[32][33];
    const int w = blockIdx.z;
    const float* W = (w == 0) ? W0 : (w == 1) ? W1 : (w == 2) ? W2 : W3;
    const int tx = threadIdx.x, ty = threadIdx.y;
#pragma unroll
    for (int i = 0; i < 4; i++)
        t[ty + 8 * i][tx] = W[(size_t)(blockIdx.y * 32 + ty + 8 * i) * QD + blockIdx.x * 32 + tx];
    __syncthreads();
#pragma unroll
    for (int i = 0; i < 4; i++) {
        int n = blockIdx.x * 32 + ty + 8 * i;
        int k = blockIdx.y * 32 + tx;
        wt[((size_t)w * QD + n) * QD + k] = __float2half(t[tx][ty + 8 * i]);
    }
}

// ======== fp16 GEMM: C[M,512] = A @ W^T, fp32 accum, 3-stage pipeline ======
#define BKC    32
#define SPADW  20                   // row stride in words (40 fp16)
#define TILEB  (128 * 80)           // 10240 B per tile
#define BUFB   (2 * TILEB)          // 20480 B per stage
#define NSTAGE 3
#define GDYN   (NSTAGE * BUFB)      // 61440 B

__device__ __forceinline__ void gemm_prefetch(
    uint32_t sbase, int b, int kc, int tid, int m0, int n0,
    const __half* Ah, const __half* Bt) {
#pragma unroll
    for (int i = 0; i < 4; i++) {
        int e = tid + i * 256;
        int tile = e >> 9;
        int r    = (e >> 2) & 127;
        int c16  = e & 3;
        uint32_t dst = sbase + b * BUFB + tile * TILEB + r * 80 + c16 * 16;
        const __half* src = (tile == 0)
            ? Ah + (size_t)(m0 + r) * QD + kc * BKC + c16 * 8
            : Bt + (size_t)(n0 + r) * QD + kc * BKC + c16 * 8;
        cp16(dst, src);
    }
    CP_COMMIT();
}

// hout=1: store fp16 to H0/H1/H2 (by z); hout=0: fp32 + bias to F.
__global__ __launch_bounds__(256, 2)
void gemm_h(const __half* __restrict__ Ah, const __half* __restrict__ Wt,
            const float* __restrict__ bias, int hout,
            __half* __restrict__ H0, __half* __restrict__ H1, __half* __restrict__ H2,
            float* __restrict__ F) {
    extern __shared__ char dsm[];
    const uint32_t sbase = smem_u32(dsm);

    const int tid = threadIdx.x;
    const int wid = tid >> 5, lid = tid & 31;
    const int wm = wid & 3, wn = wid >> 2;      // 4(m) x 2(n)
    const int g = lid >> 2, t = lid & 3;
    const int m0 = blockIdx.y * 128;
    const int n0 = blockIdx.x * 128;
    const int w  = blockIdx.z;
    const __half* Bt = Wt + (size_t)w * QD * QD;

    float acc[2][8][4];
#pragma unroll
    for (int mi = 0; mi < 2; mi++)
#pragma unroll
        for (int ni = 0; ni < 8; ni++)
#pragma unroll
            for (int c = 0; c < 4; c++) acc[mi][ni][c] = 0.0f;

    gemm_prefetch(sbase, 0, 0, tid, m0, n0, Ah, Bt);
    gemm_prefetch(sbase, 1, 1, tid, m0, n0, Ah, Bt);

    for (int kc = 0; kc < QD / BKC; kc++) {
        if (kc + 2 < QD / BKC)
            gemm_prefetch(sbase, (kc + 2) % NSTAGE, kc + 2, tid, m0, n0, Ah, Bt);
        else
            CP_COMMIT();               // empty group keeps wait arithmetic valid
        CP_WAIT2();
        __syncthreads();

        const int b = kc % NSTAGE;
        const uint32_t* AsW = (const uint32_t*)(dsm + b * BUFB);
        const uint32_t* BsW = (const uint32_t*)(dsm + b * BUFB + TILEB);

#pragma unroll
        for (int ks = 0; ks < 2; ks++) {
            const int c0w = ks * 8 + t;
            uint32_t bh[8][2];
#pragma unroll
            for (int ni = 0; ni < 8; ni++) {
                int n = wn * 64 + ni * 8 + g;
                bh[ni][0] = BsW[n * SPADW + c0w];
                bh[ni][1] = BsW[n * SPADW + c0w + 4];
            }
#pragma unroll
            for (int mi = 0; mi < 2; mi++) {
                int r = wm * 32 + mi * 16 + g;
                uint32_t ah[4];
                ah[0] = AsW[r * SPADW + c0w];
                ah[1] = AsW[(r + 8) * SPADW + c0w];
                ah[2] = AsW[r * SPADW + c0w + 4];
                ah[3] = AsW[(r + 8) * SPADW + c0w + 4];
#pragma unroll
                for (int ni = 0; ni < 8; ni++)
                    mma16816h(acc[mi][ni], ah, bh[ni]);
            }
        }
        __syncthreads();
    }

    if (hout) {
        __half* Hc = (w == 0) ? H0 : (w == 1) ? H1 : H2;
#pragma unroll
        for (int mi = 0; mi < 2; mi++) {
            int r = m0 + wm * 32 + mi * 16 + g;
#pragma unroll
            for (int ni = 0; ni < 8; ni++) {
                int col = n0 + wn * 64 + ni * 8 + t * 2;
                *(__half2*)&Hc[(size_t)r * QD + col] =
                    __floats2half2_rn(acc[mi][ni][0], acc[mi][ni][1]);
                *(__half2*)&Hc[(size_t)(r + 8) * QD + col] =
                    __floats2half2_rn(acc[mi][ni][2], acc[mi][ni][3]);
            }
        }
    } else {
#pragma unroll
        for (int mi = 0; mi < 2; mi++) {
            int r = m0 + wm * 32 + mi * 16 + g;
#pragma unroll
            for (int ni = 0; ni < 8; ni++) {
                int col = n0 + wn * 64 + ni * 8 + t * 2;
                float b0 = bias[col], b1 = bias[col + 1];
                float2 v0, v1;
                v0.x = acc[mi][ni][0] + b0; v0.y = acc[mi][ni][1] + b1;
                v1.x = acc[mi][ni][2] + b0; v1.y = acc[mi][ni][3] + b1;
                *(float2*)&F[(size_t)r * QD + col] = v0;
                *(float2*)&F[(size_t)(r + 8) * QD + col] = v1;
            }
        }
    }
}

// ---------------- Attention v5: fp16 smem tiles ----------------------------
struct Boxes { int hs[TT]; int ws[TT]; int sub_h; int sub_w; };

#define PADH 72     // halves per row (144 B; 9x16B segments -> conflict-free)

__device__ __forceinline__ float2 h2f(uint32_t h) {
    return __half22float2(*reinterpret_cast<__half2*>(&h));
}

__global__ __launch_bounds__(256)
void attn_kernel(const __half* __restrict__ QH, const __half* __restrict__ KH,
                 const __half* __restrict__ VH, const float* __restrict__ RK,
                 const float* __restrict__ RV,
                 __half* __restrict__ ATH, Boxes bx) {
    const int hw = blockIdx.x;
    const int h  = blockIdx.y;
    const int tid = threadIdx.x;

    __shared__ __half qs[TT * PADH];
    __shared__ __half ks[TT * PADH];
    __shared__ __half vs[TT * PADH];
    __shared__ __half rks[33 * PADH];
    __shared__ __half rvs[33 * PADH];
    __shared__ float sims[TT][TT + 1];

    const size_t base = ((size_t)hw * TT) * QD + h * DH;

    // stage q,k,v via cp.async (fp16 gmem -> fp16 smem, 16B chunks)
    {
        const uint32_t sq = smem_u32(qs), sk = smem_u32(ks), sv = smem_u32(vs);
#pragma unroll
        for (int e = tid; e < 384; e += 256) {
            int arr = e >> 7, idx = e & 127;
            int row = idx >> 3, c = idx & 7;
            uint32_t dst = (arr == 0 ? sq : arr == 1 ? sk : sv) + row * 144 + c * 16;
            const __half* src = (arr == 0 ? QH : arr == 1 ? KH : VH)
                                + base + (size_t)row * QD + c * 8;
            cp16(dst, src);
        }
    }
    // rel tables: fp32 gmem -> fp16 smem (converted)
    for (int e = tid; e < 33 * 64; e += 256) {
        int r = e >> 6, d = e & 63;
        rks[r * PADH + d] = __float2half(RK[e]);
        rvs[r * PADH + d] = __float2half(RV[e]);
    }
    CP_COMMIT();
    CP_WAIT0();
    __syncthreads();

    const int y = hw / 40, x = hw % 40;
    unsigned fg = 0;
#pragma unroll
    for (int t = 0; t < TT; t++) {
        int inb = (y >= bx.hs[t]) & (y < bx.hs[t] + bx.sub_h) &
                  (x >= bx.ws[t]) & (x < bx.ws[t] + bx.sub_w);
        fg |= (unsigned)inb << t;
    }

    // ---- sim: one (i,j) per thread, uint4 (8 halves) per step ----
    {
        const int i = tid >> 4, j = tid & 15;
        const int r = j - i + 16;
        float s = 0.0f, sr = 0.0f;
#pragma unroll
        for (int d8 = 0; d8 < 8; d8++) {
            uint4 qv = *(const uint4*)&qs[i * PADH + d8 * 8];
            uint4 kv = *(const uint4*)&ks[j * PADH + d8 * 8];
            uint4 rv = *(const uint4*)&rks[r * PADH + d8 * 8];
            float2 qa, ka, ra;
            qa = h2f(qv.x); ka = h2f(kv.x); ra = h2f(rv.x);
            s  = fmaf(qa.x, ka.x, s);  s  = fmaf(qa.y, ka.y, s);
            sr = fmaf(qa.x, ra.x, sr); sr = fmaf(qa.y, ra.y, sr);
            qa = h2f(qv.y); ka = h2f(kv.y); ra = h2f(rv.y);
            s  = fmaf(qa.x, ka.x, s);  s  = fmaf(qa.y, ka.y, s);
            sr = fmaf(qa.x, ra.x, sr); sr = fmaf(qa.y, ra.y, sr);
            qa = h2f(qv.z); ka = h2f(kv.z); ra = h2f(rv.z);
            s  = fmaf(qa.x, ka.x, s);  s  = fmaf(qa.y, ka.y, s);
            sr = fmaf(qa.x, ra.x, sr); sr = fmaf(qa.y, ra.y, sr);
            qa = h2f(qv.w); ka = h2f(kv.w); ra = h2f(rv.w);
            s  = fmaf(qa.x, ka.x, s);  s  = fmaf(qa.y, ka.y, s);
            sr = fmaf(qa.x, ra.x, sr); sr = fmaf(qa.y, ra.y, sr);
        }
        float m = (((fg >> i) & 1u) == ((fg >> j) & 1u)) ? 1.0f : 0.01f;
        sims[i][j] = (s + sr) * SCALE * m;
    }
    __syncthreads();

    if (tid < TT) {
        float mx = -1e30f;
#pragma unroll
        for (int j = 0; j < TT; j++) mx = fmaxf(mx, sims[tid][j]);
        float sum = 0.0f;
#pragma unroll
        for (int j = 0; j < TT; j++) {
            float e = expf(sims[tid][j] - mx);
            sims[tid][j] = e;
            sum += e;
        }
        float inv = 1.0f / sum;
#pragma unroll
        for (int j = 0; j < TT; j++) sims[tid][j] *= inv;
    }
    __syncthreads();

    // ---- out: (i, d8) on 128 threads, 8 outputs each ----
    if (tid < 128) {
        const int i = tid >> 3, d8 = tid & 7;
        float o[8];
#pragma unroll
        for (int c = 0; c < 8; c++) o[c] = 0.0f;
#pragma unroll
        for (int j = 0; j < TT; j++) {
            float s = sims[i][j];
            uint4 v4 = *(const uint4*)&vs[j * PADH + d8 * 8];
            uint4 r4 = *(const uint4*)&rvs[(j - i + 16) * PADH + d8 * 8];
            float2 va, ra;
            va = h2f(v4.x); ra = h2f(r4.x);
            o[0] = fmaf(s, va.x + ra.x, o[0]); o[1] = fmaf(s, va.y + ra.y, o[1]);
            va = h2f(v4.y); ra = h2f(r4.y);
            o[2] = fmaf(s, va.x + ra.x, o[2]); o[3] = fmaf(s, va.y + ra.y, o[3]);
            va = h2f(v4.z); ra = h2f(r4.z);
            o[4] = fmaf(s, va.x + ra.x, o[4]); o[5] = fmaf(s, va.y + ra.y, o[5]);
            va = h2f(v4.w); ra = h2f(r4.w);
            o[6] = fmaf(s, va.x + ra.x, o[6]); o[7] = fmaf(s, va.y + ra.y, o[7]);
        }
        size_t ob = base + (size_t)i * QD + d8 * 8;
        uint4 st;
        __half2 p;
        p = __floats2half2_rn(o[0], o[1]); st.x = *(uint32_t*)&p;
        p = __floats2half2_rn(o[2], o[3]); st.y = *(uint32_t*)&p;
        p = __floats2half2_rn(o[4], o[5]); st.z = *(uint32_t*)&p;
        p = __floats2half2_rn(o[6], o[7]); st.w = *(uint32_t*)&p;
        *(uint4*)&ATH[ob] = st;
    }
}

// ---------------------------- launcher -------------------------------------
extern "C" void kernel_launch(void* const* d_in, const int* in_sizes, int n_in,
                              void* d_out, int out_size) {
    const float* x     = (const float*)d_in[0];
    const float* Wq    = (const float*)d_in[1];
    const float* Wk    = (const float*)d_in[2];
    const float* Wv    = (const float*)d_in[3];
    const float* Wo    = (const float*)d_in[4];
    const float* bo    = (const float*)d_in[5];
    const float* rel_k = (const float*)d_in[6];
    const float* rel_v = (const float*)d_in[7];
    float* out = (float*)d_out;

    __half *qh, *kh, *vh, *xh, *ath, *wt;
    cudaGetSymbolAddress((void**)&qh,  g_qh);
    cudaGetSymbolAddress((void**)&kh,  g_kh);
    cudaGetSymbolAddress((void**)&vh,  g_vh);
    cudaGetSymbolAddress((void**)&xh,  g_xh);
    cudaGetSymbolAddress((void**)&ath, g_ath);
    cudaGetSymbolAddress((void**)&wt,  g_wt);

    // Box path (exact binary64 semantics): SUB_H=15, SUB_W=9
    Boxes bx;
    bx.sub_h = (int)((0.35 - 0.10) * 64.0);
    bx.sub_w = (int)((0.35 - 0.10) * 40.0);
    for (int t = 0; t < TT; t++) {
        double r  = (double)t / 15.0;
        double h0 = 0.10 + r * (0.60 - 0.10);
        double w0 = 0.10 + r * (0.60 - 0.10);
        bx.hs[t] = (int)(h0 * 64.0);
        bx.ws[t] = (int)(w0 * 40.0);
    }

    cudaFuncSetAttribute(gemm_h, cudaFuncAttributeMaxDynamicSharedMemorySize, GDYN);

    conv_x<<<MTOT * QD / 512, 256>>>(x, xh);
    conv_w<<<dim3(16, 16, 4), dim3(32, 8)>>>(Wq, Wk, Wv, Wo, wt);

    // fused QKV: fp16 outputs
    gemm_h<<<dim3(4, 320, 3), 256, GDYN>>>(xh, wt, nullptr, 1, qh, kh, vh, nullptr);

    attn_kernel<<<dim3(HW, HEADS), 256>>>(qh, kh, vh, rel_k, rel_v, ath, bx);

    // output projection: fp32 + bias
    gemm_h<<<dim3(4, 320, 1), 256, GDYN>>>(ath, wt + (size_t)3 * QD * QD,
                                           bo, 0, nullptr, nullptr, nullptr, out);
}